// round 2
// baseline (speedup 1.0000x reference)
#include <cuda_runtime.h>
#include <cuda_bf16.h>

#define BS 128
#define GS 201
#define DIM 128
#define HALF 100
#define GS2 (GS*GS)
#define OUTS (HALF + GS2)
#define NORMF 0.08838834764831845f
#define NTILES 26

// ---- device scratch (no allocations allowed) ----
__device__ float g_gmax[BS*DIM];
__device__ float g_gb[BS*DIM];
__device__ float g_h[BS*GS*DIM];
__device__ float g_hQ[BS*GS*DIM];
__device__ float g_hK[BS*GS*DIM];
__device__ float g_qW[BS*4*4*DIM];
__device__ float g_u[BS*GS*32];
__device__ float g_v[BS*GS*32];
__device__ float g_part[BS*NTILES];
__device__ float g_sums[BS];

// ---- f32x2 helpers (FFMA2 path, PTX-only) ----
__device__ __forceinline__ unsigned long long pack2(float lo, float hi){
    unsigned long long r; asm("mov.b64 %0, {%1, %2};" : "=l"(r) : "f"(lo), "f"(hi)); return r;
}
__device__ __forceinline__ float2 unpack2(unsigned long long v){
    float2 r; asm("mov.b64 {%0, %1}, %2;" : "=f"(r.x), "=f"(r.y) : "l"(v)); return r;
}
__device__ __forceinline__ unsigned long long fma2(unsigned long long a, unsigned long long b, unsigned long long c){
    unsigned long long r; asm("fma.rn.f32x2 %0, %1, %2, %3;" : "=l"(r) : "l"(a), "l"(b), "l"(c)); return r;
}
__device__ __forceinline__ unsigned long long add2(unsigned long long a, unsigned long long b){
    unsigned long long r; asm("add.rn.f32x2 %0, %1, %2;" : "=l"(r) : "l"(a), "l"(b)); return r;
}
__device__ __forceinline__ float fast_tanh(float y){
    y = fminf(fmaxf(y, -15.f), 15.f);
    float e = __expf(2.f*y);
    return __fdividef(e-1.f, e+1.f);
}

// ---- max over nodes ----
__global__ void k_gmax(const float* __restrict__ h_em){
    int b = blockIdx.x, d = threadIdx.x;
    const float* p = h_em + (size_t)b*GS*DIM + d;
    float m = -1e30f;
    for (int g = 0; g < GS; ++g) m = fmaxf(m, p[(size_t)g*DIM]);
    g_gmax[b*DIM+d] = m;
}

// ---- gb = gmax @ Wg ----
__global__ void k_gb(const float* __restrict__ Wg){
    __shared__ float xs[DIM];
    int b = blockIdx.x, c = threadIdx.x;
    xs[c] = g_gmax[b*DIM+c];
    __syncthreads();
    float acc = 0.f;
    #pragma unroll 8
    for (int i = 0; i < DIM; ++i) acc = fmaf(xs[i], Wg[i*DIM+c], acc);
    g_gb[b*DIM+c] = acc;
}

// ---- GEMM (25728x128)@(128x128). MODE0: h = h_em@Wn + gb; MODE1: hQ = h@WQr; MODE2: hK ----
template<int MODE>
__global__ __launch_bounds__(256) void k_gemm(const float* __restrict__ Aext, const float* __restrict__ B){
    __shared__ float As[64][17];
    __shared__ float Bs[16][128];
    const float* A = (MODE == 0) ? Aext : g_h;
    float* C = (MODE == 0) ? g_h : ((MODE == 1) ? g_hQ : g_hK);
    int tid = threadIdx.x;
    int tx = tid & 15, ty = tid >> 4;
    int row0 = blockIdx.x * 64;
    float acc[4][8];
    #pragma unroll
    for (int a = 0; a < 4; ++a)
        #pragma unroll
        for (int c = 0; c < 8; ++c) acc[a][c] = 0.f;
    int la_r = tid >> 2, la_k = (tid & 3)*4;
    int lb_r = tid >> 4, lb_c = (tid & 15)*8;
    for (int kc = 0; kc < DIM; kc += 16){
        float4 av = *reinterpret_cast<const float4*>(A + (size_t)(row0+la_r)*DIM + kc + la_k);
        const float* bp;
        if (MODE == 0) bp = B + (kc+lb_r)*DIM + lb_c;
        else           bp = B + (lb_c>>5)*4096 + (kc+lb_r)*32 + (lb_c&31);
        float4 bv0 = *reinterpret_cast<const float4*>(bp);
        float4 bv1 = *reinterpret_cast<const float4*>(bp+4);
        As[la_r][la_k+0]=av.x; As[la_r][la_k+1]=av.y; As[la_r][la_k+2]=av.z; As[la_r][la_k+3]=av.w;
        *reinterpret_cast<float4*>(&Bs[lb_r][lb_c])   = bv0;
        *reinterpret_cast<float4*>(&Bs[lb_r][lb_c+4]) = bv1;
        __syncthreads();
        #pragma unroll
        for (int k = 0; k < 16; ++k){
            float a0=As[ty*4+0][k], a1=As[ty*4+1][k], a2=As[ty*4+2][k], a3=As[ty*4+3][k];
            float4 b0 = *reinterpret_cast<const float4*>(&Bs[k][tx*8]);
            float4 b1 = *reinterpret_cast<const float4*>(&Bs[k][tx*8+4]);
            float bb[8] = {b0.x,b0.y,b0.z,b0.w,b1.x,b1.y,b1.z,b1.w};
            #pragma unroll
            for (int c = 0; c < 8; ++c){
                acc[0][c]=fmaf(a0,bb[c],acc[0][c]); acc[1][c]=fmaf(a1,bb[c],acc[1][c]);
                acc[2][c]=fmaf(a2,bb[c],acc[2][c]); acc[3][c]=fmaf(a3,bb[c],acc[3][c]);
            }
        }
        __syncthreads();
    }
    #pragma unroll
    for (int a = 0; a < 4; ++a){
        int row = row0 + ty*4 + a;
        #pragma unroll
        for (int c = 0; c < 8; ++c){
            float v = acc[a][c];
            if (MODE == 0) v += g_gb[(row/GS)*DIM + tx*8 + c];
            C[(size_t)row*DIM + tx*8 + c] = v;
        }
    }
}

// ---- 16 effective query vectors per batch: qW = Wk (Wq^T h_sel) ----
__global__ void k_qW(const float* __restrict__ Wq1, const float* __restrict__ Wk1,
                     const float* __restrict__ Wq2, const float* __restrict__ Wk2,
                     const int* __restrict__ fixed_action){
    int b = blockIdx.x, combo = blockIdx.y, t = threadIdx.x;
    __shared__ float xs[DIM], tmp[DIM];
    int pos = 1 + fixed_action[b*3];
    int sel = (combo & 2) ? pos + HALF : pos;
    const float* Wq = (combo & 1) ? Wq2 : Wq1;
    const float* Wk = (combo & 1) ? Wk2 : Wk1;
    xs[t] = g_h[((size_t)b*GS + sel)*DIM + t];
    __syncthreads();
    for (int hh = 0; hh < 4; ++hh){
        const float* wq = Wq + hh*DIM*DIM;
        float acc = 0.f;
        #pragma unroll 8
        for (int i = 0; i < DIM; ++i) acc = fmaf(xs[i], wq[i*DIM+t], acc);
        __syncthreads();
        tmp[t] = acc;
        __syncthreads();
        const float* wk = Wk + hh*DIM*DIM + t*DIM;
        float o = 0.f;
        #pragma unroll 8
        for (int k = 0; k < DIM; ++k) o = fmaf(tmp[k], wk[k], o);
        g_qW[((b*4+combo)*4+hh)*DIM + t] = o;
    }
}

// ---- per-node layer-1 pre-activations u (i-part) and v (j-part) ----
__global__ void k_uv(const int* __restrict__ rec, const float* __restrict__ i_w1,
                     const float* __restrict__ i_b1){
    int g = blockIdx.x, b = blockIdx.y, t = threadIdx.x;
    __shared__ float xg[DIM], xn[DIM], s[16];
    int rg = rec[b*GS + g];
    xg[t] = g_h[((size_t)b*GS + g )*DIM + t];
    xn[t] = g_h[((size_t)b*GS + rg)*DIM + t];
    __syncthreads();
    int d = t >> 3, l8 = t & 7;
    int combo = d >> 2, head = d & 3;
    const float* q = g_qW + ((b*4+combo)*4+head)*DIM;
    const float* x = (combo & 1) ? xn : xg;
    float p = 0.f;
    #pragma unroll
    for (int e = l8; e < DIM; e += 8) p = fmaf(q[e], x[e], p);
    p += __shfl_xor_sync(0xffffffffu, p, 4);
    p += __shfl_xor_sync(0xffffffffu, p, 2);
    p += __shfl_xor_sync(0xffffffffu, p, 1);
    if (l8 == 0) s[d] = p * NORMF;
    __syncthreads();
    if (t < 32){
        float u = i_b1[t];
        #pragma unroll
        for (int f = 0; f < 8; ++f) u = fmaf(s[f], i_w1[f*32+t], u);
        g_u[((size_t)b*GS + g)*32 + t] = u;
    } else if (t < 64){
        int c = t - 32;
        float v = 0.f;
        #pragma unroll
        for (int f = 0; f < 8; ++f) v = fmaf(s[8+f], i_w1[(8+f)*32+c], v);
        g_v[((size_t)b*GS + g)*32 + c] = v;
    }
}

// ---- removal scores: compat + MLP + softmax ----
__global__ void k_removal(const int* __restrict__ rec, const float* __restrict__ sig,
                          const float* __restrict__ w1, const float* __restrict__ b1,
                          const float* __restrict__ w2, const float* __restrict__ b2,
                          const float* __restrict__ w3, const float* __restrict__ b3,
                          float* __restrict__ out){
    int b = blockIdx.x, t = threadIdx.x;
    __shared__ int rec_s[GS], pre_s[GS];
    __shared__ float red[4];
    __shared__ float tot_s;
    for (int g = t; g < GS; g += 128) rec_s[g] = rec[b*GS+g];
    __syncthreads();
    for (int g = t; g < GS; g += 128) pre_s[rec_s[g]] = g;
    __syncthreads();
    float e = 0.f;
    if (t < HALF){
        float feat[12];
        #pragma unroll
        for (int hf = 0; hf < 2; ++hf){
            int g = 1 + hf*HALF + t;
            int pg = pre_s[g];
            int og = rec_s[rec_s[g]];
            const float* Qg = g_hQ + ((size_t)b*GS + g )*DIM;
            const float* Kg = g_hK + ((size_t)b*GS + g )*DIM;
            const float* Qp = g_hQ + ((size_t)b*GS + pg)*DIM;
            const float* Kp = g_hK + ((size_t)b*GS + og)*DIM;
            #pragma unroll
            for (int h = 0; h < 4; ++h){
                float c1=0.f, c2=0.f, c3=0.f;
                #pragma unroll
                for (int k = 0; k < 32; ++k){
                    float qp=Qp[h*32+k], kg=Kg[h*32+k], qg=Qg[h*32+k], kp=Kp[h*32+k];
                    c1 = fmaf(qp, kg, c1);
                    c2 = fmaf(qg, kp, c2);
                    c3 = fmaf(qp, kp, c3);
                }
                feat[hf*4+h] = c1 + c2 - c3;
            }
        }
        #pragma unroll
        for (int s4 = 0; s4 < 4; ++s4) feat[8+s4] = sig[b*4*HALF + s4*HALF + t];
        float x1[32];
        #pragma unroll
        for (int c = 0; c < 32; ++c){
            float a = b1[c];
            #pragma unroll
            for (int f = 0; f < 12; ++f) a = fmaf(feat[f], w1[f*32+c], a);
            x1[c] = fmaxf(a, 0.f);
        }
        float y = b3[0];
        #pragma unroll
        for (int o = 0; o < 32; ++o){
            float a = b2[o];
            #pragma unroll
            for (int k = 0; k < 32; ++k) a = fmaf(x1[k], w2[k*32+o], a);
            y = fmaf(fmaxf(a, 0.f), w3[o], y);
        }
        e = __expf(6.f * tanhf(y));
    }
    float w = e;
    #pragma unroll
    for (int o = 16; o; o >>= 1) w += __shfl_xor_sync(0xffffffffu, w, o);
    if ((t & 31) == 0) red[t>>5] = w;
    __syncthreads();
    if (t == 0) tot_s = red[0]+red[1]+red[2]+red[3];
    __syncthreads();
    if (t < HALF) out[(size_t)b*OUTS + t] = e / tot_s;
}

// ---- the big (b,i,j) table MLP, FFMA2 inner loop ----
__global__ __launch_bounds__(416, 1) void k_table(
        const float* __restrict__ i_w2, const float* __restrict__ i_b2,
        const float* __restrict__ i_w3, const float* __restrict__ i_b3,
        const unsigned char* __restrict__ mask, float* __restrict__ out){
    __shared__ unsigned long long w2d[32][32];
    __shared__ float vs[GS][33];
    __shared__ float us[8][32];
    __shared__ float b2s[32], w3s[32];
    __shared__ float red[16];
    int tid = threadIdx.x, b = blockIdx.y, it = blockIdx.x;

    for (int idx = tid; idx < 1024; idx += 416){
        int o = idx >> 5, k = idx & 31;
        float w = i_w2[k*32+o];
        w2d[o][k] = pack2(w, w);
    }
    if (tid < 32){ b2s[tid] = i_b2[tid]; w3s[tid] = i_w3[tid]; }
    for (int idx = tid; idx < GS*32; idx += 416)
        vs[idx>>5][idx&31] = g_v[((size_t)b*GS)*32 + idx];
    for (int idx = tid; idx < 8*32; idx += 416){
        int il = idx >> 5, k = idx & 31;
        int i = it*8 + il;
        us[il][k] = (i < GS) ? g_u[((size_t)b*GS + i)*32 + k] : 0.f;
    }
    __syncthreads();

    int jt = tid % 52, il = tid / 52;
    int i = it*8 + il;
    bool iok = (i < GS);
    float b3v = i_b3[0];
    float lsum = 0.f;
    const unsigned char* mrow = mask + ((size_t)b*GS + i)*GS;
    float* orow = out + (size_t)b*OUTS + HALF + (size_t)i*GS;

    #pragma unroll 1
    for (int p = 0; p < 2; ++p){
        int j0 = p*104 + 2*jt, j1 = j0 + 1;
        int j0c = min(j0, GS-1), j1c = min(j1, GS-1);
        unsigned long long h1[32];
        #pragma unroll
        for (int k = 0; k < 32; ++k){
            float uk = us[il][k];
            h1[k] = pack2(fmaxf(uk + vs[j0c][k], 0.f), fmaxf(uk + vs[j1c][k], 0.f));
        }
        float y0 = b3v, y1 = b3v;
        #pragma unroll 4
        for (int o = 0; o < 32; ++o){
            const unsigned long long* wrow = w2d[o];
            unsigned long long acc0 = pack2(b2s[o], b2s[o]);
            unsigned long long acc1 = 0ull;
            #pragma unroll
            for (int k = 0; k < 32; k += 2){
                acc0 = fma2(h1[k],   wrow[k],   acc0);
                acc1 = fma2(h1[k+1], wrow[k+1], acc1);
            }
            float2 r = unpack2(add2(acc0, acc1));
            y0 = fmaf(fmaxf(r.x, 0.f), w3s[o], y0);
            y1 = fmaf(fmaxf(r.y, 0.f), w3s[o], y1);
        }
        if (iok){
            if (j0 < GS){
                float e = mrow[j0] ? 0.f : __expf(6.f * fast_tanh(y0));
                orow[j0] = e; lsum += e;
            }
            if (j1 < GS){
                float e = mrow[j1] ? 0.f : __expf(6.f * fast_tanh(y1));
                orow[j1] = e; lsum += e;
            }
        }
    }
    #pragma unroll
    for (int o = 16; o; o >>= 1) lsum += __shfl_xor_sync(0xffffffffu, lsum, o);
    if ((tid & 31) == 0) red[tid>>5] = lsum;
    __syncthreads();
    if (tid == 0){
        float tot = 0.f;
        #pragma unroll
        for (int w = 0; w < 13; ++w) tot += red[w];
        g_part[b*NTILES + it] = tot;
    }
}

// ---- deterministic row sums -> reciprocal ----
__global__ void k_inv(){
    int b = blockIdx.x, t = threadIdx.x;
    float v = (t < NTILES) ? g_part[b*NTILES + t] : 0.f;
    #pragma unroll
    for (int o = 16; o; o >>= 1) v += __shfl_xor_sync(0xffffffffu, v, o);
    if (t == 0) g_sums[b] = __frcp_rn(v);
}

// ---- normalize reinsertion block ----
__global__ void k_scale(float* __restrict__ out){
    int idx = blockIdx.x*256 + threadIdx.x;
    if (idx >= BS*GS2) return;
    int b = idx / GS2;
    out[(size_t)b*OUTS + HALF + (idx - b*GS2)] *= g_sums[b];
}

extern "C" void kernel_launch(void* const* d_in, const int* in_sizes, int n_in,
                              void* d_out, int out_size) {
    const float* h_em  = (const float*)d_in[0];
    const float* sig   = (const float*)d_in[1];
    const float* Wn    = (const float*)d_in[2];
    const float* Wg    = (const float*)d_in[3];
    const float* WQr   = (const float*)d_in[4];
    const float* WKr   = (const float*)d_in[5];
    const float* r_w1  = (const float*)d_in[6];
    const float* r_b1  = (const float*)d_in[7];
    const float* r_w2  = (const float*)d_in[8];
    const float* r_b2  = (const float*)d_in[9];
    const float* r_w3  = (const float*)d_in[10];
    const float* r_b3  = (const float*)d_in[11];
    const float* Wq1   = (const float*)d_in[12];
    const float* Wk1   = (const float*)d_in[13];
    const float* Wq2   = (const float*)d_in[14];
    const float* Wk2   = (const float*)d_in[15];
    const float* i_w1  = (const float*)d_in[16];
    const float* i_b1  = (const float*)d_in[17];
    const float* i_w2  = (const float*)d_in[18];
    const float* i_b2  = (const float*)d_in[19];
    const float* i_w3  = (const float*)d_in[20];
    const float* i_b3  = (const float*)d_in[21];
    const int*   rec   = (const int*)d_in[22];
    const int*   fixed = (const int*)d_in[23];
    const unsigned char* mask = (const unsigned char*)d_in[24];
    float* out = (float*)d_out;

    k_gmax<<<BS, 128>>>(h_em);
    k_gb<<<BS, 128>>>(Wg);
    k_gemm<0><<<402, 256>>>(h_em, Wn);
    k_gemm<1><<<402, 256>>>(nullptr, WQr);
    k_gemm<2><<<402, 256>>>(nullptr, WKr);
    k_qW<<<dim3(BS, 4), 128>>>(Wq1, Wk1, Wq2, Wk2, fixed);
    k_uv<<<dim3(GS, BS), 128>>>(rec, i_w1, i_b1);
    k_removal<<<BS, 128>>>(rec, sig, r_w1, r_b1, r_w2, r_b2, r_w3, r_b3, out);
    k_table<<<dim3(NTILES, BS), 416>>>(i_w2, i_b2, i_w3, i_b3, mask, out);
    k_inv<<<BS, 32>>>();
    k_scale<<<(BS*GS2 + 255)/256, 256>>>(out);
}